// round 1
// baseline (speedup 1.0000x reference)
#include <cuda_runtime.h>
#include <cstdio>

#define B_    8
#define N_    2048
#define F_    512
#define MTOT  (B_ * N_)          // 16384
#define NEGV  (-10000.0f)
#define SLOPE 0.2f
#define FULLM 0xFFFFFFFFu

// ---------------- scratch (static device arrays: the allowed scratch path) ---
__device__ float g_hidden[(size_t)MTOT * F_];          // 33.5 MB
__device__ float g_s[MTOT];
__device__ float g_d[MTOT];
__device__ float g_P[(size_t)B_ * N_ * N_];            // 134 MB

// ---------------- packed f32x2 helpers (Blackwell: 2x fp32 FMA throughput) ---
__device__ __forceinline__ unsigned long long fma2(unsigned long long a,
                                                   unsigned long long b,
                                                   unsigned long long c) {
    unsigned long long r;
    asm("fma.rn.f32x2 %0, %1, %2, %3;" : "=l"(r) : "l"(a), "l"(b), "l"(c));
    return r;
}
__device__ __forceinline__ unsigned long long pack2(float x, float y) {
    unsigned long long r;
    asm("mov.b64 %0, {%1, %2};" : "=l"(r) : "f"(x), "f"(y));
    return r;
}
__device__ __forceinline__ float2 unpack2(unsigned long long v) {
    float2 f;
    asm("mov.b64 {%0, %1}, %2;" : "=f"(f.x), "=f"(f.y) : "l"(v));
    return f;
}

// ---------------- GEMM: C = A[M,K] @ B[K,N] (+bias), 128x128x16 tiles --------
// 256 threads, 8x8 per-thread tile as 2x2 blocks of 4x4, f32x2 packed FMA.
// All dims are exact multiples of tile sizes for this problem (no guards).
__global__ __launch_bounds__(256) void gemm_f32(
    const float* __restrict__ A, const float* __restrict__ Bm,
    const float* __restrict__ bias, float* __restrict__ C,
    int M, int N, int K,
    long long aBatch, long long bBatch, long long cBatch)
{
    __shared__ float As[16][128];   // [k][m] (transposed on store)
    __shared__ float Bs[16][128];   // [k][n]

    const float* Ab = A + (long long)blockIdx.z * aBatch;
    const float* Bb = Bm + (long long)blockIdx.z * bBatch;
    float*       Cb = C + (long long)blockIdx.z * cBatch;

    const int t = threadIdx.x;
    const int rowBase = blockIdx.y * 128;
    const int colBase = blockIdx.x * 128;

    const int ar = t >> 2;            // 0..63   (A load row)
    const int ac = (t & 3) * 4;       // 0..12   (A load col4)
    const int br = t >> 4;            // 0..15   (B load k-row)
    const int bc = (t & 15) * 4;      // 0..60   (B load col4)

    const int ty = t >> 4;            // 0..15
    const int tx = t & 15;            // 0..15

    unsigned long long acc[2][4][4];
#pragma unroll
    for (int i = 0; i < 2; i++)
#pragma unroll
        for (int j = 0; j < 4; j++)
#pragma unroll
            for (int q = 0; q < 4; q++) acc[i][j][q] = 0ULL;

    for (int k0 = 0; k0 < K; k0 += 16) {
        // A tile 128x16 -> As[k][m] (transposed). Coalesced 64B row chunks.
        float4 va0 = *(const float4*)(Ab + (size_t)(rowBase + ar) * K + k0 + ac);
        float4 va1 = *(const float4*)(Ab + (size_t)(rowBase + ar + 64) * K + k0 + ac);
        const float* p0 = (const float*)&va0;
        const float* p1 = (const float*)&va1;
#pragma unroll
        for (int q = 0; q < 4; q++) {
            As[ac + q][ar]      = p0[q];
            As[ac + q][ar + 64] = p1[q];
        }
        // B tile 16x128, direct float4 stores.
        const float* brow = Bb + (size_t)(k0 + br) * N + colBase + bc;
        *(float4*)&Bs[br][bc]      = *(const float4*)brow;
        *(float4*)&Bs[br][bc + 64] = *(const float4*)(brow + 64);

        __syncthreads();

#pragma unroll
        for (int kt = 0; kt < 16; kt++) {
            float4 a0 = *(const float4*)&As[kt][ty * 4];          // broadcast, CF
            float4 a1 = *(const float4*)&As[kt][ty * 4 + 64];
            ulonglong2 b0 = *(const ulonglong2*)&Bs[kt][tx * 4];  // 16 consecutive f4: CF
            ulonglong2 b1 = *(const ulonglong2*)&Bs[kt][tx * 4 + 64];
            const float* ae0 = (const float*)&a0;
            const float* ae1 = (const float*)&a1;
#pragma unroll
            for (int ii = 0; ii < 4; ii++) {
                unsigned long long pa0 = pack2(ae0[ii], ae0[ii]);
                acc[0][ii][0] = fma2(pa0, b0.x, acc[0][ii][0]);
                acc[0][ii][1] = fma2(pa0, b0.y, acc[0][ii][1]);
                acc[0][ii][2] = fma2(pa0, b1.x, acc[0][ii][2]);
                acc[0][ii][3] = fma2(pa0, b1.y, acc[0][ii][3]);
                unsigned long long pa1 = pack2(ae1[ii], ae1[ii]);
                acc[1][ii][0] = fma2(pa1, b0.x, acc[1][ii][0]);
                acc[1][ii][1] = fma2(pa1, b0.y, acc[1][ii][1]);
                acc[1][ii][2] = fma2(pa1, b1.x, acc[1][ii][2]);
                acc[1][ii][3] = fma2(pa1, b1.y, acc[1][ii][3]);
            }
        }
        __syncthreads();
    }

    // Epilogue (+ optional bias)
    float4 bv0 = make_float4(0.f, 0.f, 0.f, 0.f);
    float4 bv1 = make_float4(0.f, 0.f, 0.f, 0.f);
    if (bias) {
        bv0 = *(const float4*)(bias + colBase + tx * 4);
        bv1 = *(const float4*)(bias + colBase + tx * 4 + 64);
    }
#pragma unroll
    for (int ih = 0; ih < 2; ih++)
#pragma unroll
        for (int ii = 0; ii < 4; ii++) {
            int row = rowBase + ih * 64 + ty * 4 + ii;
            float* crow = Cb + (size_t)row * N + colBase + tx * 4;
            float2 q0 = unpack2(acc[ih][ii][0]);
            float2 q1 = unpack2(acc[ih][ii][1]);
            float2 q2 = unpack2(acc[ih][ii][2]);
            float2 q3 = unpack2(acc[ih][ii][3]);
            float4 o0 = make_float4(q0.x + bv0.x, q0.y + bv0.y, q1.x + bv0.z, q1.y + bv0.w);
            float4 o1 = make_float4(q2.x + bv1.x, q2.y + bv1.y, q3.x + bv1.z, q3.y + bv1.w);
            *(float4*)crow        = o0;
            *(float4*)(crow + 64) = o1;
        }
}

// ---------------- per-row scores: s = h.a_src, d = h.a_dst -------------------
__global__ __launch_bounds__(128) void sd_kernel(
    const float* __restrict__ hidden, const float* __restrict__ a_src,
    const float* __restrict__ a_dst, float* __restrict__ s, float* __restrict__ d)
{
    int row = blockIdx.x;
    int t = threadIdx.x;                       // 128 threads, 4 cols each
    float4 hv = ((const float4*)(hidden + (size_t)row * F_))[t];
    float4 av = ((const float4*)a_src)[t];
    float4 dv = ((const float4*)a_dst)[t];
    float ss = hv.x * av.x + hv.y * av.y + hv.z * av.z + hv.w * av.w;
    float dd = hv.x * dv.x + hv.y * dv.y + hv.z * dv.z + hv.w * dv.w;
#pragma unroll
    for (int o = 16; o; o >>= 1) {
        ss += __shfl_xor_sync(FULLM, ss, o);
        dd += __shfl_xor_sync(FULLM, dd, o);
    }
    __shared__ float rs[4], rd[4];
    int lane = t & 31, wid = t >> 5;
    if (lane == 0) { rs[wid] = ss; rd[wid] = dd; }
    __syncthreads();
    if (t == 0) {
        s[row] = rs[0] + rs[1] + rs[2] + rs[3];
        d[row] = rd[0] + rd[1] + rd[2] + rd[3];
    }
}

// ---------------- softmax probabilities: P[row, j] ---------------------------
// One block per (b, i) row. 256 threads x 8 j's kept in registers across the
// max / sumexp / write phases: adj is read exactly once.
__global__ __launch_bounds__(256) void prob_kernel(
    const int* __restrict__ adj, const float* __restrict__ s,
    const float* __restrict__ dvec, float* __restrict__ P)
{
    int row = blockIdx.x;                 // 0..16383
    int t = threadIdx.x;
    const int*   arow = adj + (size_t)row * N_;
    const float* drow = dvec + ((row >> 11) << 11);
    float si = s[row];

    float sc[8];
#pragma unroll
    for (int q = 0; q < 8; q++) {
        int j = t + q * 256;
        float x = si + drow[j];
        x = (x >= 0.0f) ? x : SLOPE * x;            // LeakyReLU
        sc[q] = arow[j] ? NEGV : x;                 // mask overrides
    }

    __shared__ float redA[8], redB[8];
    int lane = t & 31, wid = t >> 5;

    // block max
    float m = sc[0];
#pragma unroll
    for (int q = 1; q < 8; q++) m = fmaxf(m, sc[q]);
#pragma unroll
    for (int o = 16; o; o >>= 1) m = fmaxf(m, __shfl_xor_sync(FULLM, m, o));
    if (lane == 0) redA[wid] = m;
    __syncthreads();
    if (wid == 0) {
        float v = (lane < 8) ? redA[lane] : -3.4e38f;
#pragma unroll
        for (int o = 16; o; o >>= 1) v = fmaxf(v, __shfl_xor_sync(FULLM, v, o));
        if (lane == 0) redA[0] = v;
    }
    __syncthreads();
    m = redA[0];

    // block sum of exp(sc - m)  (masked lanes underflow to exactly 0, same as ref)
    float l = 0.0f;
#pragma unroll
    for (int q = 0; q < 8; q++) { sc[q] = __expf(sc[q] - m); l += sc[q]; }
#pragma unroll
    for (int o = 16; o; o >>= 1) l += __shfl_xor_sync(FULLM, l, o);
    if (lane == 0) redB[wid] = l;
    __syncthreads();
    if (wid == 0) {
        float v = (lane < 8) ? redB[lane] : 0.0f;
#pragma unroll
        for (int o = 16; o; o >>= 1) v += __shfl_xor_sync(FULLM, v, o);
        if (lane == 0) redB[0] = v;
    }
    __syncthreads();
    float inv = 1.0f / redB[0];

    float* prow = P + (size_t)row * N_;
#pragma unroll
    for (int q = 0; q < 8; q++) prow[t + q * 256] = sc[q] * inv;
}

// ---------------- launch -----------------------------------------------------
extern "C" void kernel_launch(void* const* d_in, const int* in_sizes, int n_in,
                              void* d_out, int out_size) {
    (void)in_sizes; (void)n_in; (void)out_size;
    const float* text  = (const float*)d_in[0];
    const int*   adj   = (const int*)d_in[1];
    const float* W     = (const float*)d_in[2];
    const float* bias  = (const float*)d_in[3];
    const float* a_src = (const float*)d_in[4];
    const float* a_dst = (const float*)d_in[5];
    float* out = (float*)d_out;

    float *hid, *sv, *dv, *P;
    cudaGetSymbolAddress((void**)&hid, g_hidden);
    cudaGetSymbolAddress((void**)&sv,  g_s);
    cudaGetSymbolAddress((void**)&dv,  g_d);
    cudaGetSymbolAddress((void**)&P,   g_P);

    // 1) hidden = text @ W + b        [16384,512] x [512,512]
    gemm_f32<<<dim3(F_ / 128, MTOT / 128, 1), 256>>>(
        text, W, bias, hid, MTOT, F_, F_, 0LL, 0LL, 0LL);

    // 2) s, d per node
    sd_kernel<<<MTOT, 128>>>(hid, a_src, a_dst, sv, dv);

    // 3) softmax probabilities P
    prob_kernel<<<MTOT, 256>>>(adj, sv, dv, P);

    // 4) out = P @ hidden (batched over B)
    gemm_f32<<<dim3(F_ / 128, N_ / 128, B_), 256>>>(
        P, hid, nullptr, out, N_, F_, N_,
        (long long)N_ * N_, (long long)N_ * F_, (long long)N_ * F_);
}

// round 3
// speedup vs baseline: 1.9217x; 1.9217x over previous
#include <cuda_runtime.h>
#include <cuda_bf16.h>
#include <cstdint>

#define B_    8
#define N_    2048
#define F_    512
#define MTOT  (B_ * N_)          // 16384
#define NEGV  (-10000.0f)
#define SLOPE 0.2f
#define FULLM 0xFFFFFFFFu

// ---------------- device scratch (sanctioned static-array path) -------------
__device__ __nv_bfloat16 g_tHi[(size_t)MTOT * F_];
__device__ __nv_bfloat16 g_tLo[(size_t)MTOT * F_];
__device__ __nv_bfloat16 g_WHi[(size_t)F_ * F_];
__device__ __nv_bfloat16 g_WLo[(size_t)F_ * F_];
__device__ __nv_bfloat16 g_hHi[(size_t)MTOT * F_];   // hidden split, row-major
__device__ __nv_bfloat16 g_hLo[(size_t)MTOT * F_];
__device__ float g_sv[MTOT], g_dv[MTOT];
__device__ __nv_bfloat16 g_PHi[(size_t)MTOT * N_];
__device__ __nv_bfloat16 g_PLo[(size_t)MTOT * N_];

// ---------------- base-target PTX helpers ------------------------------------
__device__ __forceinline__ uint32_t smem_u32(const void* p) {
    uint32_t a;
    asm("{ .reg .u64 t; cvta.to.shared.u64 t, %1; cvt.u32.u64 %0, t; }"
        : "=r"(a) : "l"(p));
    return a;
}
__device__ __forceinline__ void cp16(uint32_t dst, const void* src) {
    asm volatile("cp.async.cg.shared.global [%0], [%1], 16;" :: "r"(dst), "l"(src));
}
#define CP_COMMIT() asm volatile("cp.async.commit_group;" ::: "memory")
#define CP_WAIT(n)  asm volatile("cp.async.wait_group %0;" :: "n"(n) : "memory")

#define LDSM4(r0, r1, r2, r3, addr) \
    asm volatile("ldmatrix.sync.aligned.m8n8.x4.shared.b16 {%0,%1,%2,%3}, [%4];" \
                 : "=r"(r0), "=r"(r1), "=r"(r2), "=r"(r3) : "r"(addr))
#define LDSM4T(r0, r1, r2, r3, addr) \
    asm volatile("ldmatrix.sync.aligned.m8n8.x4.trans.shared.b16 {%0,%1,%2,%3}, [%4];" \
                 : "=r"(r0), "=r"(r1), "=r"(r2), "=r"(r3) : "r"(addr))

#define MMA(d, a, b) \
    asm volatile("mma.sync.aligned.m16n8k16.row.col.f32.bf16.bf16.f32 " \
                 "{%0,%1,%2,%3}, {%4,%5,%6,%7}, {%8,%9}, {%0,%1,%2,%3};" \
                 : "+f"((d)[0]), "+f"((d)[1]), "+f"((d)[2]), "+f"((d)[3]) \
                 : "r"((a)[0]), "r"((a)[1]), "r"((a)[2]), "r"((a)[3]), \
                   "r"((b)[0]), "r"((b)[1]))

// ---------------- SMEM layout -------------------------------------------------
// A tile: 128 rows x 32 bf16, pitch 40 bf16 (80 B) -> conflict-free ldmatrix
// B tile:  32 rows x 128 bf16, pitch 136 bf16 (272 B)
#define A_PITCH_B 80
#define B_PITCH_B 272
#define SZ_A (128 * A_PITCH_B)            // 10240
#define SZ_B (32 * B_PITCH_B)             // 8704
#define BUF_STRIDE (2 * SZ_A + 2 * SZ_B)  // 37888
#define SMEM_BYTES (2 * BUF_STRIDE)       // 75776

// ---------------- 3-term split-bf16 GEMM (mma.sync), CTA 128x128x32 ----------
// C[m,n] = sum_k (Ahi+Alo)[m,k] * (Bhi+Blo)[k,n]   (lo*lo term dropped)
// mode 0: h = C + bias -> split into (hHi, hLo), row-major [row][512]
// mode 1: outF[row][512] = C  (fp32)
__global__ __launch_bounds__(256) void gemm_mma(
    const __nv_bfloat16* __restrict__ Ahi, const __nv_bfloat16* __restrict__ Alo,
    const __nv_bfloat16* __restrict__ Bhi, const __nv_bfloat16* __restrict__ Blo,
    int lda, int ldb, int K, int AZ, int BZ, int mode,
    const float* __restrict__ bias, float* __restrict__ outF,
    __nv_bfloat16* __restrict__ hHi, __nv_bfloat16* __restrict__ hLo)
{
    extern __shared__ char sm[];
    const uint32_t smBase = smem_u32(sm);

    const int t = threadIdx.x;
    const int warp = t >> 5, lane = t & 31;
    const int wm = warp & 1, wn = warp >> 1;          // 2 x 4 warp grid

    const int nBase  = blockIdx.x * 128;
    const int aRow0  = blockIdx.y * 128 + blockIdx.z * AZ;
    const int bRow0  = blockIdx.z * BZ;

    float acc[4][4][4];
#pragma unroll
    for (int i = 0; i < 4; i++)
#pragma unroll
        for (int j = 0; j < 4; j++)
#pragma unroll
            for (int q = 0; q < 4; q++) acc[i][j][q] = 0.0f;

    // ---- tile loader (cp.async, 8 x 16B per thread) ----
    auto load_tile = [&](int buf, int kpos) {
        uint32_t ob = smBase + buf * BUF_STRIDE;
#pragma unroll
        for (int i = 0; i < 2; i++) {                 // A: 512 chunks x (hi,lo)
            int idx = t + i * 256;
            int r = idx >> 2, ch = idx & 3;
            size_t g = (size_t)(aRow0 + r) * lda + kpos + ch * 8;
            uint32_t d = ob + r * A_PITCH_B + ch * 16;
            cp16(d,        Ahi + g);
            cp16(d + SZ_A, Alo + g);
        }
#pragma unroll
        for (int i = 0; i < 2; i++) {                 // B: 512 chunks x (hi,lo)
            int idx = t + i * 256;
            int r = idx >> 4, ch = idx & 15;
            size_t g = (size_t)(bRow0 + kpos + r) * ldb + nBase + ch * 8;
            uint32_t d = ob + 2 * SZ_A + r * B_PITCH_B + ch * 16;
            cp16(d,        Bhi + g);
            cp16(d + SZ_B, Blo + g);
        }
    };

    // per-lane ldmatrix address components
    const int aRowL  = lane & 15;                     // + wm*64 + mt*16
    const int aColB  = (lane >> 4) * 16;              // byte offset within k16
    const int bRowL  = lane & 15;                     // + ks*16
    const int bColB  = (wn * 32 + (lane >> 4) * 8) * 2;  // + bt*32 bytes

    const int ntiles = K / 32;
    load_tile(0, 0);
    CP_COMMIT();

    for (int kt = 0; kt < ntiles; kt++) {
        if (kt + 1 < ntiles) {
            load_tile((kt + 1) & 1, (kt + 1) * 32);
            CP_COMMIT();
            CP_WAIT(1);
        } else {
            CP_WAIT(0);
        }
        __syncthreads();

        const uint32_t ob  = smBase + (kt & 1) * BUF_STRIDE;
        const uint32_t obB = ob + 2 * SZ_A;

#pragma unroll
        for (int ks = 0; ks < 2; ks++) {
            uint32_t ahi[4][4], alo[4][4];
#pragma unroll
            for (int mt = 0; mt < 4; mt++) {
                uint32_t ra = ob + (wm * 64 + mt * 16 + aRowL) * A_PITCH_B
                            + ks * 32 + aColB;
                LDSM4(ahi[mt][0], ahi[mt][1], ahi[mt][2], ahi[mt][3], ra);
                LDSM4(alo[mt][0], alo[mt][1], alo[mt][2], alo[mt][3], ra + SZ_A);
            }
            uint32_t bhi[4][2], blo[4][2];
#pragma unroll
            for (int bt = 0; bt < 2; bt++) {
                uint32_t rb = obB + (ks * 16 + bRowL) * B_PITCH_B + bColB + bt * 32;
                LDSM4T(bhi[bt*2][0], bhi[bt*2][1], bhi[bt*2+1][0], bhi[bt*2+1][1], rb);
                LDSM4T(blo[bt*2][0], blo[bt*2][1], blo[bt*2+1][0], blo[bt*2+1][1],
                       rb + SZ_B);
            }
#pragma unroll
            for (int mt = 0; mt < 4; mt++)
#pragma unroll
                for (int nt = 0; nt < 4; nt++) {
                    MMA(acc[mt][nt], ahi[mt], bhi[nt]);
                    MMA(acc[mt][nt], alo[mt], bhi[nt]);
                    MMA(acc[mt][nt], ahi[mt], blo[nt]);
                }
        }
        __syncthreads();
    }

    // ---------------- epilogue ----------------
#pragma unroll
    for (int nt = 0; nt < 4; nt++) {
        int gCol = nBase + wn * 32 + nt * 8 + (lane & 3) * 2;
        float2 bv = make_float2(0.f, 0.f);
        if (mode == 0) bv = *(const float2*)(bias + gCol);
#pragma unroll
        for (int mt = 0; mt < 4; mt++) {
            int gRow = aRow0 + wm * 64 + mt * 16 + (lane >> 2);
            if (mode == 1) {
                *(float2*)(outF + (size_t)gRow * F_ + gCol) =
                    make_float2(acc[mt][nt][0], acc[mt][nt][1]);
                *(float2*)(outF + (size_t)(gRow + 8) * F_ + gCol) =
                    make_float2(acc[mt][nt][2], acc[mt][nt][3]);
            } else {
#pragma unroll
                for (int h = 0; h < 2; h++) {
                    float h0 = acc[mt][nt][h * 2]     + bv.x;
                    float h1 = acc[mt][nt][h * 2 + 1] + bv.y;
                    __nv_bfloat16 hi0 = __float2bfloat16(h0);
                    __nv_bfloat16 hi1 = __float2bfloat16(h1);
                    __nv_bfloat162 vh; vh.x = hi0; vh.y = hi1;
                    __nv_bfloat162 vl;
                    vl.x = __float2bfloat16(h0 - __bfloat162float(hi0));
                    vl.y = __float2bfloat16(h1 - __bfloat162float(hi1));
                    size_t o = (size_t)(gRow + h * 8) * F_ + gCol;
                    *(__nv_bfloat162*)(hHi + o) = vh;
                    *(__nv_bfloat162*)(hLo + o) = vl;
                }
            }
        }
    }
}

// ---------------- prep: split fp32 -> bf16 hi/lo ------------------------------
__global__ __launch_bounds__(256) void split_f32(const float* __restrict__ x,
                                                 __nv_bfloat16* __restrict__ hi,
                                                 __nv_bfloat16* __restrict__ lo) {
    size_t i = (size_t)blockIdx.x * 256 + threadIdx.x;   // one float4 each
    float4 v = ((const float4*)x)[i];
    __nv_bfloat16 h0 = __float2bfloat16(v.x), h1 = __float2bfloat16(v.y);
    __nv_bfloat16 h2 = __float2bfloat16(v.z), h3 = __float2bfloat16(v.w);
    __nv_bfloat162* ph = (__nv_bfloat162*)(hi + i * 4);
    __nv_bfloat162* pl = (__nv_bfloat162*)(lo + i * 4);
    __nv_bfloat162 a, b, c, d;
    a.x = h0; a.y = h1; b.x = h2; b.y = h3;
    c.x = __float2bfloat16(v.x - __bfloat162float(h0));
    c.y = __float2bfloat16(v.y - __bfloat162float(h1));
    d.x = __float2bfloat16(v.z - __bfloat162float(h2));
    d.y = __float2bfloat16(v.w - __bfloat162float(h3));
    ph[0] = a; ph[1] = b; pl[0] = c; pl[1] = d;
}

// ---------------- s/d per node from split hidden ------------------------------
__global__ __launch_bounds__(128) void sd_kernel(
    const __nv_bfloat16* __restrict__ hHi, const __nv_bfloat16* __restrict__ hLo,
    const float* __restrict__ a_src, const float* __restrict__ a_dst,
    float* __restrict__ s, float* __restrict__ d)
{
    int row = blockIdx.x;
    int t = threadIdx.x;                         // 4 cols per thread
    const __nv_bfloat162* ph = (const __nv_bfloat162*)(hHi + (size_t)row * F_) + t * 2;
    const __nv_bfloat162* pl = (const __nv_bfloat162*)(hLo + (size_t)row * F_) + t * 2;
    __nv_bfloat162 h0 = ph[0], h1 = ph[1], l0 = pl[0], l1 = pl[1];
    float4 av = ((const float4*)a_src)[t];
    float4 dv = ((const float4*)a_dst)[t];
    float hv0 = __bfloat162float(h0.x) + __bfloat162float(l0.x);
    float hv1 = __bfloat162float(h0.y) + __bfloat162float(l0.y);
    float hv2 = __bfloat162float(h1.x) + __bfloat162float(l1.x);
    float hv3 = __bfloat162float(h1.y) + __bfloat162float(l1.y);
    float ss = hv0 * av.x + hv1 * av.y + hv2 * av.z + hv3 * av.w;
    float dd = hv0 * dv.x + hv1 * dv.y + hv2 * dv.z + hv3 * dv.w;
#pragma unroll
    for (int o = 16; o; o >>= 1) {
        ss += __shfl_xor_sync(FULLM, ss, o);
        dd += __shfl_xor_sync(FULLM, dd, o);
    }
    __shared__ float rs[4], rd[4];
    int lane = t & 31, wid = t >> 5;
    if (lane == 0) { rs[wid] = ss; rd[wid] = dd; }
    __syncthreads();
    if (t == 0) {
        s[row] = rs[0] + rs[1] + rs[2] + rs[3];
        d[row] = rd[0] + rd[1] + rd[2] + rd[3];
    }
}

// ---------------- softmax probabilities -> split bf16 -------------------------
__global__ __launch_bounds__(256) void prob_kernel(
    const int* __restrict__ adj, const float* __restrict__ s,
    const float* __restrict__ dvec,
    __nv_bfloat16* __restrict__ Phi, __nv_bfloat16* __restrict__ Plo)
{
    int row = blockIdx.x;
    int t = threadIdx.x;
    const int*   arow = adj + (size_t)row * N_;
    const float* drow = dvec + ((row >> 11) << 11);
    float si = s[row];

    float sc[8];
#pragma unroll
    for (int q = 0; q < 8; q++) {
        int j = t + q * 256;
        float x = si + drow[j];
        x = (x >= 0.0f) ? x : SLOPE * x;
        sc[q] = arow[j] ? NEGV : x;
    }
    __shared__ float redA[8], redB[8];
    int lane = t & 31, wid = t >> 5;
    float m = sc[0];
#pragma unroll
    for (int q = 1; q < 8; q++) m = fmaxf(m, sc[q]);
#pragma unroll
    for (int o = 16; o; o >>= 1) m = fmaxf(m, __shfl_xor_sync(FULLM, m, o));
    if (lane == 0) redA[wid] = m;
    __syncthreads();
    if (wid == 0) {
        float v = (lane < 8) ? redA[lane] : -3.4e38f;
#pragma unroll
        for (int o = 16; o; o >>= 1) v = fmaxf(v, __shfl_xor_sync(FULLM, v, o));
        if (lane == 0) redA[0] = v;
    }
    __syncthreads();
    m = redA[0];

    float l = 0.0f;
#pragma unroll
    for (int q = 0; q < 8; q++) { sc[q] = __expf(sc[q] - m); l += sc[q]; }
#pragma unroll
    for (int o = 16; o; o >>= 1) l += __shfl_xor_sync(FULLM, l, o);
    if (lane == 0) redB[wid] = l;
    __syncthreads();
    if (wid == 0) {
        float v = (lane < 8) ? redB[lane] : 0.0f;
#pragma unroll
        for (int o = 16; o; o >>= 1) v += __shfl_xor_sync(FULLM, v, o);
        if (lane == 0) redB[0] = v;
    }
    __syncthreads();
    float inv = 1.0f / redB[0];

    __nv_bfloat16* ph = Phi + (size_t)row * N_;
    __nv_bfloat16* pl = Plo + (size_t)row * N_;
#pragma unroll
    for (int q = 0; q < 8; q++) {
        float p = sc[q] * inv;
        __nv_bfloat16 hi = __float2bfloat16(p);
        ph[t + q * 256] = hi;
        pl[t + q * 256] = __float2bfloat16(p - __bfloat162float(hi));
    }
}

// ---------------- launch -------------------------------------------------------
extern "C" void kernel_launch(void* const* d_in, const int* in_sizes, int n_in,
                              void* d_out, int out_size) {
    (void)in_sizes; (void)n_in; (void)out_size;
    const float* text  = (const float*)d_in[0];
    const int*   adj   = (const int*)d_in[1];
    const float* W     = (const float*)d_in[2];
    const float* bias  = (const float*)d_in[3];
    const float* a_src = (const float*)d_in[4];
    const float* a_dst = (const float*)d_in[5];
    float* out = (float*)d_out;

    __nv_bfloat16 *tHi, *tLo, *WHi, *WLo, *hHi, *hLo, *PHi, *PLo;
    float *sv, *dv;
    cudaGetSymbolAddress((void**)&tHi, g_tHi);
    cudaGetSymbolAddress((void**)&tLo, g_tLo);
    cudaGetSymbolAddress((void**)&WHi, g_WHi);
    cudaGetSymbolAddress((void**)&WLo, g_WLo);
    cudaGetSymbolAddress((void**)&hHi, g_hHi);
    cudaGetSymbolAddress((void**)&hLo, g_hLo);
    cudaGetSymbolAddress((void**)&sv,  g_sv);
    cudaGetSymbolAddress((void**)&dv,  g_dv);
    cudaGetSymbolAddress((void**)&PHi, g_PHi);
    cudaGetSymbolAddress((void**)&PLo, g_PLo);

    static int smem_set = 0;
    if (!smem_set) {
        cudaFuncSetAttribute(gemm_mma, cudaFuncAttributeMaxDynamicSharedMemorySize,
                             SMEM_BYTES);
        smem_set = 1;
    }

    // 0) precision splits
    split_f32<<<(MTOT * F_ / 4) / 256, 256>>>(text, tHi, tLo);
    split_f32<<<(F_ * F_ / 4) / 256, 256>>>(W, WHi, WLo);

    // 1) hidden = text @ W + b   (A: text [16384,512], B: W [512,512])
    gemm_mma<<<dim3(F_ / 128, MTOT / 128, 1), 256, SMEM_BYTES>>>(
        tHi, tLo, WHi, WLo, F_, F_, F_, 0, 0, 0,
        bias, nullptr, hHi, hLo);

    // 2) s, d per node
    sd_kernel<<<MTOT, 128>>>(hHi, hLo, a_src, a_dst, sv, dv);

    // 3) softmax probabilities -> split bf16
    prob_kernel<<<MTOT, 256>>>(adj, sv, dv, PHi, PLo);

    // 4) out = P @ hidden   (A: P [2048,2048] per batch, B: hidden [2048,512])
    gemm_mma<<<dim3(F_ / 128, N_ / 128, B_), 256, SMEM_BYTES>>>(
        PHi, PLo, hHi, hLo, N_, F_, N_, N_, N_, 1,
        nullptr, out, nullptr, nullptr);
}